// round 11
// baseline (speedup 1.0000x reference)
#include <cuda_runtime.h>
#include <cuda_bf16.h>
#include <math.h>
#include <stdint.h>

// ---------------------------------------------------------------------------
// FraudGraphSAGE: 2-layer GraphSAGE (mean agg) + FC sigmoid head.
// Aggregation: slot-CSR gather (fixed 64 slots/node, no f32 atomics).
// GEMMs: mma.sync m16n8k16 bf16-split (hi/lo), fp32 accumulate.
//   M-tile 256/CTA, 512 threads, A via contiguous LDG.128 (custom logical<->
//   physical k permutation shared with the W image), B via conflict-free
//   LDS.128 with hi/lo interleaved. No mainloop barriers.
// ---------------------------------------------------------------------------

#define NMAX 100000
#define SLOTS 64

__device__ float4 g_agg4[(size_t)NMAX * 32];
__device__ float4 g_h14[(size_t)NMAX * 32];
__device__ int    g_fill[NMAX];
__device__ int    g_csr[(size_t)NMAX * SLOTS];
__device__ int    g_idx_is64;
// W image per layer: [n=128][1088B]: per ksg (64B): 4x16B sub-blocks
//   sub-block t4 = [hi(4t4..4t4+3) | lo(4t4..4t4+3)] bf16. 139264B/layer.
__device__ uint4  g_wimg[2][8704];

// ======================= helpers ===========================================
__device__ __forceinline__ uint32_t smem_u32(const void* p) {
    uint32_t a;
    asm("{ .reg .u64 t; cvta.to.shared.u64 t, %1; cvt.u32.u64 %0, t; }"
        : "=r"(a) : "l"(p));
    return a;
}
__device__ __forceinline__ void lds128(uint4& v, uint32_t addr) {
    asm volatile("ld.shared.v4.b32 {%0,%1,%2,%3}, [%4];"
                 : "=r"(v.x), "=r"(v.y), "=r"(v.z), "=r"(v.w) : "r"(addr));
}
__device__ __forceinline__ void mma_bf16(float* c, uint32_t a0, uint32_t a1,
                                         uint32_t a2, uint32_t a3,
                                         uint32_t b0, uint32_t b1) {
    asm volatile(
        "mma.sync.aligned.m16n8k16.row.col.f32.bf16.bf16.f32 "
        "{%0,%1,%2,%3}, {%4,%5,%6,%7}, {%8,%9}, {%0,%1,%2,%3};"
        : "+f"(c[0]), "+f"(c[1]), "+f"(c[2]), "+f"(c[3])
        : "r"(a0), "r"(a1), "r"(a2), "r"(a3), "r"(b0), "r"(b1));
}
// float2 -> (bf16x2 hi, bf16x2 lo)
__device__ __forceinline__ void cvt_hl(float x, float y, uint32_t& hi, uint32_t& lo) {
    __nv_bfloat16 h0 = __float2bfloat16(x);
    __nv_bfloat16 h1 = __float2bfloat16(y);
    __nv_bfloat162 hp = __halves2bfloat162(h0, h1);
    __nv_bfloat162 lp = __floats2bfloat162_rn(
        x - __bfloat162float(h0), y - __bfloat162float(h1));
    hi = *(uint32_t*)&hp;
    lo = *(uint32_t*)&lp;
}

__device__ __forceinline__ int edge_dst(const void* ei, int E, int e, int is64)
{
    if (is64) return (int)__ldg(((const long long*)ei) + E + e);
    return __ldg(((const int*)ei) + E + e);
}
__device__ __forceinline__ int edge_src(const void* ei, int E, int e, int is64)
{
    if (is64) return (int)__ldg(((const long long*)ei) + e);
    return __ldg(((const int*)ei) + e);
}

// ======================= setup: probe + zero fill + W prep =================
__global__ void setup_prep_kernel(const void* ei, int n,
                                  const float* __restrict__ W1l, const float* __restrict__ W1r,
                                  const float* __restrict__ W2l, const float* __restrict__ W2r)
{
    int t = blockIdx.x * blockDim.x + threadIdx.x;
    if (t < n) g_fill[t] = 0;
    if (t == 0) {
        const unsigned long long* p = (const unsigned long long*)ei;
        int is64 = 1;
        for (int k = 0; k < 8; k++)
            if (p[k] >> 32) { is64 = 0; break; }
        g_idx_is64 = is64;
    }
    if (t < 2 * 128 * 256) {
        int layer = t >> 15;
        int rem = t & 32767;
        int nrow = rem >> 8;
        int k = rem & 255;          // physical reduction index
        const float* Wl = layer ? W2l : W1l;
        const float* Wr = layer ? W2r : W1r;
        float v = (k < 128) ? __ldg(Wl + k * 128 + nrow)
                            : __ldg(Wr + (k - 128) * 128 + nrow);
        __nv_bfloat16 hh = __float2bfloat16(v);
        __nv_bfloat16 ll = __float2bfloat16(v - __bfloat162float(hh));
        int ksg = k >> 4, j = k & 15;
        uint32_t off = (uint32_t)nrow * 1088 + ksg * 64 + (j >> 2) * 16 + (j & 3) * 2;
        *(__nv_bfloat16*)((char*)&g_wimg[layer][0] + off) = hh;
        *(__nv_bfloat16*)((char*)&g_wimg[layer][0] + off + 8) = ll;
    }
}

// fill slot-CSR; g_fill ends up holding the degree
__global__ void fill_kernel(const void* __restrict__ ei, int E)
{
    int is64 = g_idx_is64;
    int tid = blockIdx.x * blockDim.x + threadIdx.x;
    int stride = gridDim.x * blockDim.x;
    for (int e = tid; e < E; e += stride) {
        int d = edge_dst(ei, E, e, is64);
        int s = edge_src(ei, E, e, is64);
        int slot = atomicAdd(&g_fill[d], 1);
        if (slot < SLOTS) g_csr[(size_t)d * SLOTS + slot] = s;
    }
}

// ======================= Gather (mean aggregate) ===========================
__global__ void gather_kernel(const float* __restrict__ feat, int n)
{
    int lane = threadIdx.x & 31;
    int w = (blockIdx.x * blockDim.x + threadIdx.x) >> 5;
    if (w >= n) return;
    const int* lst = g_csr + (size_t)w * SLOTS;
    int cnt = min(g_fill[w], SLOTS);
    const float4* f4 = (const float4*)feat;
    float4 a0 = make_float4(0.f, 0.f, 0.f, 0.f), a1 = a0, a2 = a0, a3 = a0;
    int j = 0;
    for (; j + 4 <= cnt; j += 4) {
        int s0 = __ldg(lst + j);
        int s1 = __ldg(lst + j + 1);
        int s2 = __ldg(lst + j + 2);
        int s3 = __ldg(lst + j + 3);
        float4 v0 = __ldg(f4 + (size_t)s0 * 32 + lane);
        float4 v1 = __ldg(f4 + (size_t)s1 * 32 + lane);
        float4 v2 = __ldg(f4 + (size_t)s2 * 32 + lane);
        float4 v3 = __ldg(f4 + (size_t)s3 * 32 + lane);
        a0.x += v0.x; a0.y += v0.y; a0.z += v0.z; a0.w += v0.w;
        a1.x += v1.x; a1.y += v1.y; a1.z += v1.z; a1.w += v1.w;
        a2.x += v2.x; a2.y += v2.y; a2.z += v2.z; a2.w += v2.w;
        a3.x += v3.x; a3.y += v3.y; a3.z += v3.z; a3.w += v3.w;
    }
    for (; j < cnt; j++) {
        int s = __ldg(lst + j);
        float4 v = __ldg(f4 + (size_t)s * 32 + lane);
        a0.x += v.x; a0.y += v.y; a0.z += v.z; a0.w += v.w;
    }
    float inv = 1.0f / fmaxf((float)cnt, 1.0f);
    float4 rr;
    rr.x = (a0.x + a1.x + a2.x + a3.x) * inv;
    rr.y = (a0.y + a1.y + a2.y + a3.y) * inv;
    rr.z = (a0.z + a1.z + a2.z + a3.z) * inv;
    rr.w = (a0.w + a1.w + a2.w + a3.w) * inv;
    g_agg4[(size_t)w * 32 + lane] = rr;
}

// ======================= mma.sync GEMM =====================================
// C[i][0:128] = relu([agg_i | A2_i](256) @ W(256x128) + bias), bf16 split:
// A_hi*W_hi + A_lo*W_hi + A_hi*W_lo, fp32 accum.
// 512 thr, 16 warps: wm=wid&7 -> m32 (mi=2), wn=wid>>3 -> n64 (ni=8).
// Lane t4 owns physical k {4t4..4t4+3} per 16-k step (A via one LDG.128/row);
// W image stores matching 16B sub-blocks -> one LDS.128 per B fragment.
#define OFF_BIAS 139264
#define OFF_WFC  139776
#define OFF_FC   140288
#define MMA_SMEM 141312

template <int EPI>
__global__ __launch_bounds__(512, 1)
void mma_gemm_kernel(const float* __restrict__ A2, const uint4* __restrict__ wimg,
                     const float* __restrict__ bias, const float* __restrict__ wfc,
                     const float* __restrict__ bfc, float* __restrict__ out, int nn)
{
    extern __shared__ char smem[];
    uint32_t sb = smem_u32(smem);
    const int tid = threadIdx.x;
    const int lane = tid & 31, wid = tid >> 5;
    const int g = lane >> 2, t4 = lane & 3;
    const int wm = wid & 7, wn = wid >> 3;
    const int rowBase = blockIdx.x * 256;
    float* bias_s = (float*)(smem + OFF_BIAS);
    float* wfc_s  = (float*)(smem + OFF_WFC);
    float* fc_s   = (float*)(smem + OFF_FC);

    // stage W image (8704 uint4)
    {
        uint4* dst = (uint4*)smem;
#pragma unroll
        for (int i = 0; i < 17; i++) {
            int idx = tid + 512 * i;
            dst[idx] = __ldg(wimg + idx);
        }
    }
    if (tid < 128) {
        bias_s[tid] = __ldg(bias + tid);
        wfc_s[tid] = EPI ? __ldg(wfc + tid) : 0.f;
    }
    if (EPI && tid < 256) fc_s[tid] = 0.f;
    __syncthreads();

    const float* aggp = (const float*)g_agg4;

    float acc[2][8][4];
#pragma unroll
    for (int mi = 0; mi < 2; mi++)
#pragma unroll
        for (int ni = 0; ni < 8; ni++)
#pragma unroll
            for (int q = 0; q < 4; q++) acc[mi][ni][q] = 0.f;

    const float4 fz4 = make_float4(0.f, 0.f, 0.f, 0.f);

    for (int ksg = 0; ksg < 16; ksg++) {
        const float* base = (ksg < 8) ? aggp : A2;
        const int f4off = (ksg & 7) * 4 + t4;   // float4 index within row
        // A fragments for this k-step (one LDG.128 per row)
        uint32_t ah[2][4], al[2][4];
#pragma unroll
        for (int mi = 0; mi < 2; mi++) {
            int row0 = rowBase + wm * 32 + mi * 16 + g;
            int row1 = row0 + 8;
            float4 F0 = (row0 < nn)
                ? __ldg((const float4*)(base + (size_t)row0 * 128) + f4off) : fz4;
            float4 F1 = (row1 < nn)
                ? __ldg((const float4*)(base + (size_t)row1 * 128) + f4off) : fz4;
            cvt_hl(F0.x, F0.y, ah[mi][0], al[mi][0]);
            cvt_hl(F1.x, F1.y, ah[mi][1], al[mi][1]);
            cvt_hl(F0.z, F0.w, ah[mi][2], al[mi][2]);
            cvt_hl(F1.z, F1.w, ah[mi][3], al[mi][3]);
        }
#pragma unroll
        for (int ni = 0; ni < 8; ni++) {
            uint4 B;
            lds128(B, sb + (uint32_t)(wn * 64 + ni * 8 + g) * 1088
                        + ksg * 64 + t4 * 16);
#pragma unroll
            for (int mi = 0; mi < 2; mi++) {
                mma_bf16(acc[mi][ni], ah[mi][0], ah[mi][1], ah[mi][2], ah[mi][3],
                         B.x, B.y);
                mma_bf16(acc[mi][ni], al[mi][0], al[mi][1], al[mi][2], al[mi][3],
                         B.x, B.y);
                mma_bf16(acc[mi][ni], ah[mi][0], ah[mi][1], ah[mi][2], ah[mi][3],
                         B.z, B.w);
            }
        }
    }

    // ---- epilogue ----
    if (EPI == 0) {
#pragma unroll
        for (int mi = 0; mi < 2; mi++)
#pragma unroll
            for (int ni = 0; ni < 8; ni++) {
                int rowA = rowBase + wm * 32 + mi * 16 + g;
                int nf = wn * 64 + ni * 8 + 2 * t4;
                float b0 = bias_s[nf], b1 = bias_s[nf + 1];
                float v0 = fmaxf(acc[mi][ni][0] + b0, 0.f);
                float v1 = fmaxf(acc[mi][ni][1] + b1, 0.f);
                float v2 = fmaxf(acc[mi][ni][2] + b0, 0.f);
                float v3 = fmaxf(acc[mi][ni][3] + b1, 0.f);
                if (rowA < nn)
                    *(float2*)(out + (size_t)rowA * 128 + nf) = make_float2(v0, v1);
                if (rowA + 8 < nn)
                    *(float2*)(out + (size_t)(rowA + 8) * 128 + nf) = make_float2(v2, v3);
            }
    } else {
#pragma unroll
        for (int mi = 0; mi < 2; mi++) {
            float pA = 0.f, pB = 0.f;
#pragma unroll
            for (int ni = 0; ni < 8; ni++) {
                int nf = wn * 64 + ni * 8 + 2 * t4;
                float b0 = bias_s[nf], b1 = bias_s[nf + 1];
                float w0 = wfc_s[nf], w1 = wfc_s[nf + 1];
                pA += fmaxf(acc[mi][ni][0] + b0, 0.f) * w0
                    + fmaxf(acc[mi][ni][1] + b1, 0.f) * w1;
                pB += fmaxf(acc[mi][ni][2] + b0, 0.f) * w0
                    + fmaxf(acc[mi][ni][3] + b1, 0.f) * w1;
            }
            pA += __shfl_xor_sync(0xffffffffu, pA, 1);
            pA += __shfl_xor_sync(0xffffffffu, pA, 2);
            pB += __shfl_xor_sync(0xffffffffu, pB, 1);
            pB += __shfl_xor_sync(0xffffffffu, pB, 2);
            if (t4 == 0) {
                atomicAdd(&fc_s[wm * 32 + mi * 16 + g], pA);
                atomicAdd(&fc_s[wm * 32 + mi * 16 + g + 8], pB);
            }
        }
        __syncthreads();
        if (tid < 256) {
            int row = rowBase + tid;
            if (row < nn)
                out[row] = 1.0f / (1.0f + __expf(-(fc_s[tid] + __ldg(bfc))));
        }
    }
}

// ======================= launch sequence ===================================
extern "C" void kernel_launch(void* const* d_in, const int* in_sizes, int n_in,
                              void* d_out, int out_size)
{
    const float* x   = (const float*)d_in[0];
    const void*  ei  = d_in[1];
    const float* W1l = (const float*)d_in[2];
    const float* W1r = (const float*)d_in[3];
    const float* b1  = (const float*)d_in[4];
    const float* W2l = (const float*)d_in[5];
    const float* W2r = (const float*)d_in[6];
    const float* b2  = (const float*)d_in[7];
    const float* Wfc = (const float*)d_in[8];
    const float* bfc = (const float*)d_in[9];
    float*       out = (float*)d_out;

    int n = in_sizes[0] / 128;
    int E = in_sizes[1] / 2;

    float* h1_ptr = nullptr;
    cudaGetSymbolAddress((void**)&h1_ptr, g_h14);
    uint4* wimg_ptr = nullptr;
    cudaGetSymbolAddress((void**)&wimg_ptr, g_wimg);

    cudaFuncSetAttribute(mma_gemm_kernel<0>,
                         cudaFuncAttributeMaxDynamicSharedMemorySize, MMA_SMEM);
    cudaFuncSetAttribute(mma_gemm_kernel<1>,
                         cudaFuncAttributeMaxDynamicSharedMemorySize, MMA_SMEM);

    int gemmBlocks = (n + 255) / 256;
    int nb = (n + 255) / 256;
    int gatherBlocks = (n * 32 + 255) / 256;

    // setup (probe + zero fill + W prep), then slot-CSR fill
    setup_prep_kernel<<<nb, 256>>>(ei, n, W1l, W1r, W2l, W2r);   // 0
    fill_kernel<<<1024, 256>>>(ei, E);                            // 1

    // layer 1
    gather_kernel<<<gatherBlocks, 256>>>(x, n);                   // 2
    mma_gemm_kernel<0><<<gemmBlocks, 512, MMA_SMEM>>>(            // 3 <- ncu
        x, wimg_ptr, b1, nullptr, nullptr, h1_ptr, n);

    // layer 2 + FC head
    gather_kernel<<<gatherBlocks, 256>>>(h1_ptr, n);              // 4
    mma_gemm_kernel<1><<<gemmBlocks, 512, MMA_SMEM>>>(            // 5
        h1_ptr, wimg_ptr + 8704, b2, Wfc, bfc, out, n);
}

// round 12
// speedup vs baseline: 1.0561x; 1.0561x over previous
#include <cuda_runtime.h>
#include <cuda_bf16.h>
#include <math.h>
#include <stdint.h>

// ---------------------------------------------------------------------------
// FraudGraphSAGE: 2-layer GraphSAGE (mean agg) + FC sigmoid head.
// Aggregation: slot-CSR gather (fixed 64 slots/node, no f32 atomics).
// GEMMs: mma.sync m16n8k16 bf16-split (hi/lo), fp32 accumulate.
//   M-tile 256/CTA, 512 threads. A via one LDG.128/row/kstep using a
//   logical<->physical k permutation (lane t4 owns phys k 4t4..4t4+3);
//   B via conflict-free LDS.64 pairs from separate hi/lo W images laid out
//   with the same permutation. No mainloop barriers.
// ---------------------------------------------------------------------------

#define NMAX 100000
#define SLOTS 64

__device__ float4 g_agg4[(size_t)NMAX * 32];
__device__ float4 g_h14[(size_t)NMAX * 32];
__device__ int    g_fill[NMAX];
__device__ int    g_csr[(size_t)NMAX * SLOTS];
__device__ int    g_idx_is64;
// W images: [layer][hi=0/lo=1][69632B]: [n=128][544B]: per ksg (32B):
//   4x8B sub-blocks; sub-block t4 = bf16 phys k {4t4,4t4+1,4t4+2,4t4+3}.
__device__ uint4  g_wimg[2][2][4352];

// ======================= helpers ===========================================
__device__ __forceinline__ uint32_t smem_u32(const void* p) {
    uint32_t a;
    asm("{ .reg .u64 t; cvta.to.shared.u64 t, %1; cvt.u32.u64 %0, t; }"
        : "=r"(a) : "l"(p));
    return a;
}
__device__ __forceinline__ void lds64(uint32_t& x, uint32_t& y, uint32_t addr) {
    asm volatile("ld.shared.v2.b32 {%0,%1}, [%2];" : "=r"(x), "=r"(y) : "r"(addr));
}
__device__ __forceinline__ void mma_bf16(float* c, uint32_t a0, uint32_t a1,
                                         uint32_t a2, uint32_t a3,
                                         uint32_t b0, uint32_t b1) {
    asm volatile(
        "mma.sync.aligned.m16n8k16.row.col.f32.bf16.bf16.f32 "
        "{%0,%1,%2,%3}, {%4,%5,%6,%7}, {%8,%9}, {%0,%1,%2,%3};"
        : "+f"(c[0]), "+f"(c[1]), "+f"(c[2]), "+f"(c[3])
        : "r"(a0), "r"(a1), "r"(a2), "r"(a3), "r"(b0), "r"(b1));
}
// (x,y) -> (bf16x2 hi, bf16x2 lo)
__device__ __forceinline__ void cvt_hl(float x, float y, uint32_t& hi, uint32_t& lo) {
    __nv_bfloat16 h0 = __float2bfloat16(x);
    __nv_bfloat16 h1 = __float2bfloat16(y);
    __nv_bfloat162 hp = __halves2bfloat162(h0, h1);
    __nv_bfloat162 lp = __floats2bfloat162_rn(
        x - __bfloat162float(h0), y - __bfloat162float(h1));
    hi = *(uint32_t*)&hp;
    lo = *(uint32_t*)&lp;
}

__device__ __forceinline__ int edge_dst(const void* ei, int E, int e, int is64)
{
    if (is64) return (int)__ldg(((const long long*)ei) + E + e);
    return __ldg(((const int*)ei) + E + e);
}
__device__ __forceinline__ int edge_src(const void* ei, int E, int e, int is64)
{
    if (is64) return (int)__ldg(((const long long*)ei) + e);
    return __ldg(((const int*)ei) + e);
}

// ======================= setup: probe + zero fill + W prep =================
__global__ void setup_prep_kernel(const void* ei, int n,
                                  const float* __restrict__ W1l, const float* __restrict__ W1r,
                                  const float* __restrict__ W2l, const float* __restrict__ W2r)
{
    int t = blockIdx.x * blockDim.x + threadIdx.x;
    if (t < n) g_fill[t] = 0;
    if (t == 0) {
        const unsigned long long* p = (const unsigned long long*)ei;
        int is64 = 1;
        for (int k = 0; k < 8; k++)
            if (p[k] >> 32) { is64 = 0; break; }
        g_idx_is64 = is64;
    }
    if (t < 2 * 128 * 256) {
        int layer = t >> 15;
        int rem = t & 32767;
        int nrow = rem >> 8;
        int k = rem & 255;          // physical reduction index
        const float* Wl = layer ? W2l : W1l;
        const float* Wr = layer ? W2r : W1r;
        float v = (k < 128) ? __ldg(Wl + k * 128 + nrow)
                            : __ldg(Wr + (k - 128) * 128 + nrow);
        __nv_bfloat16 hh = __float2bfloat16(v);
        __nv_bfloat16 ll = __float2bfloat16(v - __bfloat162float(hh));
        int ksg = k >> 4, j = k & 15;
        // sub-block (j>>2)=t4 gets phys k 4*t4 + (j&3)
        uint32_t off = (uint32_t)nrow * 544 + ksg * 32 + (j >> 2) * 8 + (j & 3) * 2;
        *(__nv_bfloat16*)((char*)&g_wimg[layer][0][0] + off) = hh;
        *(__nv_bfloat16*)((char*)&g_wimg[layer][1][0] + off) = ll;
    }
}

// fill slot-CSR; g_fill ends up holding the degree
__global__ void fill_kernel(const void* __restrict__ ei, int E)
{
    int is64 = g_idx_is64;
    int tid = blockIdx.x * blockDim.x + threadIdx.x;
    int stride = gridDim.x * blockDim.x;
    for (int e = tid; e < E; e += stride) {
        int d = edge_dst(ei, E, e, is64);
        int s = edge_src(ei, E, e, is64);
        int slot = atomicAdd(&g_fill[d], 1);
        if (slot < SLOTS) g_csr[(size_t)d * SLOTS + slot] = s;
    }
}

// ======================= Gather (mean aggregate) ===========================
__global__ void gather_kernel(const float* __restrict__ feat, int n)
{
    int lane = threadIdx.x & 31;
    int w = (blockIdx.x * blockDim.x + threadIdx.x) >> 5;
    if (w >= n) return;
    const int* lst = g_csr + (size_t)w * SLOTS;
    int cnt = min(g_fill[w], SLOTS);
    const float4* f4 = (const float4*)feat;
    float4 a0 = make_float4(0.f, 0.f, 0.f, 0.f), a1 = a0, a2 = a0, a3 = a0;
    int j = 0;
    for (; j + 4 <= cnt; j += 4) {
        int s0 = __ldg(lst + j);
        int s1 = __ldg(lst + j + 1);
        int s2 = __ldg(lst + j + 2);
        int s3 = __ldg(lst + j + 3);
        float4 v0 = __ldg(f4 + (size_t)s0 * 32 + lane);
        float4 v1 = __ldg(f4 + (size_t)s1 * 32 + lane);
        float4 v2 = __ldg(f4 + (size_t)s2 * 32 + lane);
        float4 v3 = __ldg(f4 + (size_t)s3 * 32 + lane);
        a0.x += v0.x; a0.y += v0.y; a0.z += v0.z; a0.w += v0.w;
        a1.x += v1.x; a1.y += v1.y; a1.z += v1.z; a1.w += v1.w;
        a2.x += v2.x; a2.y += v2.y; a2.z += v2.z; a2.w += v2.w;
        a3.x += v3.x; a3.y += v3.y; a3.z += v3.z; a3.w += v3.w;
    }
    for (; j < cnt; j++) {
        int s = __ldg(lst + j);
        float4 v = __ldg(f4 + (size_t)s * 32 + lane);
        a0.x += v.x; a0.y += v.y; a0.z += v.z; a0.w += v.w;
    }
    float inv = 1.0f / fmaxf((float)cnt, 1.0f);
    float4 rr;
    rr.x = (a0.x + a1.x + a2.x + a3.x) * inv;
    rr.y = (a0.y + a1.y + a2.y + a3.y) * inv;
    rr.z = (a0.z + a1.z + a2.z + a3.z) * inv;
    rr.w = (a0.w + a1.w + a2.w + a3.w) * inv;
    g_agg4[(size_t)w * 32 + lane] = rr;
}

// ======================= mma.sync GEMM =====================================
// C[i][0:128] = relu([agg_i | A2_i](256) @ W(256x128) + bias), bf16 split:
// A_hi*W_hi + A_lo*W_hi + A_hi*W_lo, fp32 accum.
// 512 thr, 16 warps: wm=wid&7 -> m32 (mi=2), wn=wid>>3 -> n64 (ni=8).
#define OFF_W_HI 0
#define OFF_W_LO 69632
#define OFF_BIAS 139264
#define OFF_WFC  139776
#define OFF_FC   140288
#define MMA_SMEM 141312

template <int EPI>
__global__ __launch_bounds__(512, 1)
void mma_gemm_kernel(const float* __restrict__ A2, const uint4* __restrict__ wimg,
                     const float* __restrict__ bias, const float* __restrict__ wfc,
                     const float* __restrict__ bfc, float* __restrict__ out, int nn)
{
    extern __shared__ char smem[];
    uint32_t sb = smem_u32(smem);
    const int tid = threadIdx.x;
    const int lane = tid & 31, wid = tid >> 5;
    const int g = lane >> 2, t4 = lane & 3;
    const int wm = wid & 7, wn = wid >> 3;
    const int rowBase = blockIdx.x * 256;
    float* bias_s = (float*)(smem + OFF_BIAS);
    float* wfc_s  = (float*)(smem + OFF_WFC);
    float* fc_s   = (float*)(smem + OFF_FC);

    // stage W images (hi + lo contiguous: 8704 uint4)
    {
        uint4* dst = (uint4*)smem;
#pragma unroll
        for (int i = 0; i < 17; i++) {
            int idx = tid + 512 * i;
            dst[idx] = __ldg(wimg + idx);
        }
    }
    if (tid < 128) {
        bias_s[tid] = __ldg(bias + tid);
        wfc_s[tid] = EPI ? __ldg(wfc + tid) : 0.f;
    }
    if (EPI && tid < 256) fc_s[tid] = 0.f;
    __syncthreads();

    const float* aggp = (const float*)g_agg4;

    float acc[2][8][4];
#pragma unroll
    for (int mi = 0; mi < 2; mi++)
#pragma unroll
        for (int ni = 0; ni < 8; ni++)
#pragma unroll
            for (int q = 0; q < 4; q++) acc[mi][ni][q] = 0.f;

    const float4 fz4 = make_float4(0.f, 0.f, 0.f, 0.f);

    for (int ksg = 0; ksg < 16; ksg++) {
        const float* base = (ksg < 8) ? aggp : A2;
        const int f4off = (ksg & 7) * 4 + t4;   // float4 index within row
        // A fragments: one LDG.128 per row; lane t4 = phys k {4t4..4t4+3}
        uint32_t ah[2][4], al[2][4];
#pragma unroll
        for (int mi = 0; mi < 2; mi++) {
            int row0 = rowBase + wm * 32 + mi * 16 + g;
            int row1 = row0 + 8;
            float4 F0 = (row0 < nn)
                ? __ldg((const float4*)(base + (size_t)row0 * 128) + f4off) : fz4;
            float4 F1 = (row1 < nn)
                ? __ldg((const float4*)(base + (size_t)row1 * 128) + f4off) : fz4;
            cvt_hl(F0.x, F0.y, ah[mi][0], al[mi][0]);
            cvt_hl(F1.x, F1.y, ah[mi][1], al[mi][1]);
            cvt_hl(F0.z, F0.w, ah[mi][2], al[mi][2]);
            cvt_hl(F1.z, F1.w, ah[mi][3], al[mi][3]);
        }
#pragma unroll
        for (int ni = 0; ni < 8; ni++) {
            uint2 BH, BL;
            uint32_t bo = (uint32_t)(wn * 64 + ni * 8 + g) * 544
                        + ksg * 32 + t4 * 8;
            lds64(BH.x, BH.y, sb + OFF_W_HI + bo);
            lds64(BL.x, BL.y, sb + OFF_W_LO + bo);
#pragma unroll
            for (int mi = 0; mi < 2; mi++) {
                mma_bf16(acc[mi][ni], ah[mi][0], ah[mi][1], ah[mi][2], ah[mi][3],
                         BH.x, BH.y);
                mma_bf16(acc[mi][ni], al[mi][0], al[mi][1], al[mi][2], al[mi][3],
                         BH.x, BH.y);
                mma_bf16(acc[mi][ni], ah[mi][0], ah[mi][1], ah[mi][2], ah[mi][3],
                         BL.x, BL.y);
            }
        }
    }

    // ---- epilogue ----
    if (EPI == 0) {
#pragma unroll
        for (int mi = 0; mi < 2; mi++)
#pragma unroll
            for (int ni = 0; ni < 8; ni++) {
                int rowA = rowBase + wm * 32 + mi * 16 + g;
                int nf = wn * 64 + ni * 8 + 2 * t4;
                float b0 = bias_s[nf], b1 = bias_s[nf + 1];
                float v0 = fmaxf(acc[mi][ni][0] + b0, 0.f);
                float v1 = fmaxf(acc[mi][ni][1] + b1, 0.f);
                float v2 = fmaxf(acc[mi][ni][2] + b0, 0.f);
                float v3 = fmaxf(acc[mi][ni][3] + b1, 0.f);
                if (rowA < nn)
                    *(float2*)(out + (size_t)rowA * 128 + nf) = make_float2(v0, v1);
                if (rowA + 8 < nn)
                    *(float2*)(out + (size_t)(rowA + 8) * 128 + nf) = make_float2(v2, v3);
            }
    } else {
#pragma unroll
        for (int mi = 0; mi < 2; mi++) {
            float pA = 0.f, pB = 0.f;
#pragma unroll
            for (int ni = 0; ni < 8; ni++) {
                int nf = wn * 64 + ni * 8 + 2 * t4;
                float b0 = bias_s[nf], b1 = bias_s[nf + 1];
                float w0 = wfc_s[nf], w1 = wfc_s[nf + 1];
                pA += fmaxf(acc[mi][ni][0] + b0, 0.f) * w0
                    + fmaxf(acc[mi][ni][1] + b1, 0.f) * w1;
                pB += fmaxf(acc[mi][ni][2] + b0, 0.f) * w0
                    + fmaxf(acc[mi][ni][3] + b1, 0.f) * w1;
            }
            pA += __shfl_xor_sync(0xffffffffu, pA, 1);
            pA += __shfl_xor_sync(0xffffffffu, pA, 2);
            pB += __shfl_xor_sync(0xffffffffu, pB, 1);
            pB += __shfl_xor_sync(0xffffffffu, pB, 2);
            if (t4 == 0) {
                atomicAdd(&fc_s[wm * 32 + mi * 16 + g], pA);
                atomicAdd(&fc_s[wm * 32 + mi * 16 + g + 8], pB);
            }
        }
        __syncthreads();
        if (tid < 256) {
            int row = rowBase + tid;
            if (row < nn)
                out[row] = 1.0f / (1.0f + __expf(-(fc_s[tid] + __ldg(bfc))));
        }
    }
}

// ======================= launch sequence ===================================
extern "C" void kernel_launch(void* const* d_in, const int* in_sizes, int n_in,
                              void* d_out, int out_size)
{
    const float* x   = (const float*)d_in[0];
    const void*  ei  = d_in[1];
    const float* W1l = (const float*)d_in[2];
    const float* W1r = (const float*)d_in[3];
    const float* b1  = (const float*)d_in[4];
    const float* W2l = (const float*)d_in[5];
    const float* W2r = (const float*)d_in[6];
    const float* b2  = (const float*)d_in[7];
    const float* Wfc = (const float*)d_in[8];
    const float* bfc = (const float*)d_in[9];
    float*       out = (float*)d_out;

    int n = in_sizes[0] / 128;
    int E = in_sizes[1] / 2;

    float* h1_ptr = nullptr;
    cudaGetSymbolAddress((void**)&h1_ptr, g_h14);
    uint4* wimg_ptr = nullptr;
    cudaGetSymbolAddress((void**)&wimg_ptr, g_wimg);

    cudaFuncSetAttribute(mma_gemm_kernel<0>,
                         cudaFuncAttributeMaxDynamicSharedMemorySize, MMA_SMEM);
    cudaFuncSetAttribute(mma_gemm_kernel<1>,
                         cudaFuncAttributeMaxDynamicSharedMemorySize, MMA_SMEM);

    int gemmBlocks = (n + 255) / 256;
    int nb = (n + 255) / 256;
    int gatherBlocks = (n * 32 + 255) / 256;

    // setup (probe + zero fill + W prep), then slot-CSR fill
    setup_prep_kernel<<<nb, 256>>>(ei, n, W1l, W1r, W2l, W2r);   // 0
    fill_kernel<<<1024, 256>>>(ei, E);                            // 1

    // layer 1
    gather_kernel<<<gatherBlocks, 256>>>(x, n);                   // 2
    mma_gemm_kernel<0><<<gemmBlocks, 512, MMA_SMEM>>>(            // 3 <- ncu
        x, wimg_ptr, b1, nullptr, nullptr, h1_ptr, n);

    // layer 2 + FC head
    gather_kernel<<<gatherBlocks, 256>>>(h1_ptr, n);              // 4
    mma_gemm_kernel<1><<<gemmBlocks, 512, MMA_SMEM>>>(            // 5
        h1_ptr, wimg_ptr + 8704, b2, Wfc, bfc, out, n);
}

// round 13
// speedup vs baseline: 1.1312x; 1.0711x over previous
#include <cuda_runtime.h>
#include <cuda_bf16.h>
#include <math.h>
#include <stdint.h>

// ---------------------------------------------------------------------------
// FraudGraphSAGE: 2-layer GraphSAGE (mean agg) + FC sigmoid head.
// Aggregation: slot-CSR gather (fixed 64 slots/node, no f32 atomics).
// GEMMs: mma.sync m16n8k16 bf16-split (hi=truncate/lo=residual), fp32 accum.
//   M-tile 256/CTA, 512 threads. A via one LDG.128/row/kstep (logical<->
//   physical k permutation shared with the W image); B via conflict-free
//   LDS.64 pairs. Mainloop split per A-source and fully unrolled so ptxas
//   pipelines the A loads. No mainloop barriers.
// ---------------------------------------------------------------------------

#define NMAX 100000
#define SLOTS 64

__device__ float4 g_agg4[(size_t)NMAX * 32];
__device__ float4 g_h14[(size_t)NMAX * 32];
__device__ int    g_fill[NMAX];
__device__ int    g_csr[(size_t)NMAX * SLOTS];
__device__ int    g_idx_is64;
// W images: [layer][hi=0/lo=1][69632B]: [n=128][544B]: per ksg (32B):
//   4x8B sub-blocks; sub-block t4 = bf16 phys k {4t4,4t4+1,4t4+2,4t4+3}.
__device__ uint4  g_wimg[2][2][4352];

// ======================= helpers ===========================================
__device__ __forceinline__ uint32_t smem_u32(const void* p) {
    uint32_t a;
    asm("{ .reg .u64 t; cvta.to.shared.u64 t, %1; cvt.u32.u64 %0, t; }"
        : "=r"(a) : "l"(p));
    return a;
}
__device__ __forceinline__ void lds64(uint32_t& x, uint32_t& y, uint32_t addr) {
    asm volatile("ld.shared.v2.b32 {%0,%1}, [%2];" : "=r"(x), "=r"(y) : "r"(addr));
}
__device__ __forceinline__ void mma_bf16(float* c, uint32_t a0, uint32_t a1,
                                         uint32_t a2, uint32_t a3,
                                         uint32_t b0, uint32_t b1) {
    asm volatile(
        "mma.sync.aligned.m16n8k16.row.col.f32.bf16.bf16.f32 "
        "{%0,%1,%2,%3}, {%4,%5,%6,%7}, {%8,%9}, {%0,%1,%2,%3};"
        : "+f"(c[0]), "+f"(c[1]), "+f"(c[2]), "+f"(c[3])
        : "r"(a0), "r"(a1), "r"(a2), "r"(a3), "r"(b0), "r"(b1));
}
// (x,y) -> (bf16x2 hi, bf16x2 lo).  hi = truncated top-16-bits (one PRMT for
// the pair); lo = rn(residual) via packed cvt. Residual is exact, so total
// split error ~2^-17 per value.
__device__ __forceinline__ void cvt_hl(float x, float y, uint32_t& hi, uint32_t& lo) {
    uint32_t xu = __float_as_uint(x), yu = __float_as_uint(y);
    asm("prmt.b32 %0, %1, %2, 0x7632;" : "=r"(hi) : "r"(xu), "r"(yu));
    float lx = x - __uint_as_float(xu & 0xFFFF0000u);
    float ly = y - __uint_as_float(yu & 0xFFFF0000u);
    asm("cvt.rn.bf16x2.f32 %0, %1, %2;" : "=r"(lo) : "f"(ly), "f"(lx));
}

__device__ __forceinline__ int edge_dst(const void* ei, int E, int e, int is64)
{
    if (is64) return (int)__ldg(((const long long*)ei) + E + e);
    return __ldg(((const int*)ei) + E + e);
}
__device__ __forceinline__ int edge_src(const void* ei, int E, int e, int is64)
{
    if (is64) return (int)__ldg(((const long long*)ei) + e);
    return __ldg(((const int*)ei) + e);
}

// ======================= setup: probe + zero fill + W prep =================
__global__ void setup_prep_kernel(const void* ei, int n,
                                  const float* __restrict__ W1l, const float* __restrict__ W1r,
                                  const float* __restrict__ W2l, const float* __restrict__ W2r)
{
    int t = blockIdx.x * blockDim.x + threadIdx.x;
    if (t < n) g_fill[t] = 0;
    if (t == 0) {
        const unsigned long long* p = (const unsigned long long*)ei;
        int is64 = 1;
        for (int k = 0; k < 8; k++)
            if (p[k] >> 32) { is64 = 0; break; }
        g_idx_is64 = is64;
    }
    if (t < 2 * 128 * 256) {
        int layer = t >> 15;
        int rem = t & 32767;
        int nrow = rem >> 8;
        int k = rem & 255;          // physical reduction index
        const float* Wl = layer ? W2l : W1l;
        const float* Wr = layer ? W2r : W1r;
        float v = (k < 128) ? __ldg(Wl + k * 128 + nrow)
                            : __ldg(Wr + (k - 128) * 128 + nrow);
        __nv_bfloat16 hh = __float2bfloat16(v);
        __nv_bfloat16 ll = __float2bfloat16(v - __bfloat162float(hh));
        int ksg = k >> 4, j = k & 15;
        // sub-block (j>>2)=t4 gets phys k 4*t4 + (j&3)
        uint32_t off = (uint32_t)nrow * 544 + ksg * 32 + (j >> 2) * 8 + (j & 3) * 2;
        *(__nv_bfloat16*)((char*)&g_wimg[layer][0][0] + off) = hh;
        *(__nv_bfloat16*)((char*)&g_wimg[layer][1][0] + off) = ll;
    }
}

// fill slot-CSR; g_fill ends up holding the degree
__global__ void fill_kernel(const void* __restrict__ ei, int E)
{
    int is64 = g_idx_is64;
    int tid = blockIdx.x * blockDim.x + threadIdx.x;
    int stride = gridDim.x * blockDim.x;
    for (int e = tid; e < E; e += stride) {
        int d = edge_dst(ei, E, e, is64);
        int s = edge_src(ei, E, e, is64);
        int slot = atomicAdd(&g_fill[d], 1);
        if (slot < SLOTS) g_csr[(size_t)d * SLOTS + slot] = s;
    }
}

// ======================= Gather (mean aggregate) ===========================
__global__ void gather_kernel(const float* __restrict__ feat, int n)
{
    int lane = threadIdx.x & 31;
    int w = (blockIdx.x * blockDim.x + threadIdx.x) >> 5;
    if (w >= n) return;
    const int* lst = g_csr + (size_t)w * SLOTS;
    int cnt = min(g_fill[w], SLOTS);
    const float4* f4 = (const float4*)feat;
    float4 a0 = make_float4(0.f, 0.f, 0.f, 0.f), a1 = a0, a2 = a0, a3 = a0;
    int j = 0;
    for (; j + 4 <= cnt; j += 4) {
        int s0 = __ldg(lst + j);
        int s1 = __ldg(lst + j + 1);
        int s2 = __ldg(lst + j + 2);
        int s3 = __ldg(lst + j + 3);
        float4 v0 = __ldg(f4 + (size_t)s0 * 32 + lane);
        float4 v1 = __ldg(f4 + (size_t)s1 * 32 + lane);
        float4 v2 = __ldg(f4 + (size_t)s2 * 32 + lane);
        float4 v3 = __ldg(f4 + (size_t)s3 * 32 + lane);
        a0.x += v0.x; a0.y += v0.y; a0.z += v0.z; a0.w += v0.w;
        a1.x += v1.x; a1.y += v1.y; a1.z += v1.z; a1.w += v1.w;
        a2.x += v2.x; a2.y += v2.y; a2.z += v2.z; a2.w += v2.w;
        a3.x += v3.x; a3.y += v3.y; a3.z += v3.z; a3.w += v3.w;
    }
    for (; j < cnt; j++) {
        int s = __ldg(lst + j);
        float4 v = __ldg(f4 + (size_t)s * 32 + lane);
        a0.x += v.x; a0.y += v.y; a0.z += v.z; a0.w += v.w;
    }
    float inv = 1.0f / fmaxf((float)cnt, 1.0f);
    float4 rr;
    rr.x = (a0.x + a1.x + a2.x + a3.x) * inv;
    rr.y = (a0.y + a1.y + a2.y + a3.y) * inv;
    rr.z = (a0.z + a1.z + a2.z + a3.z) * inv;
    rr.w = (a0.w + a1.w + a2.w + a3.w) * inv;
    g_agg4[(size_t)w * 32 + lane] = rr;
}

// ======================= mma.sync GEMM =====================================
// C[i][0:128] = relu([agg_i | A2_i](256) @ W(256x128) + bias), bf16 split:
// A_hi*W_hi + A_lo*W_hi + A_hi*W_lo, fp32 accum.
// 512 thr, 16 warps: wm=wid&7 -> m32 (mi=2), wn=wid>>3 -> n64 (ni=8).
#define OFF_W_HI 0
#define OFF_W_LO 69632
#define OFF_BIAS 139264
#define OFF_WFC  139776
#define OFF_FC   140288
#define MMA_SMEM 141312

template <int EPI>
__global__ __launch_bounds__(512, 1)
void mma_gemm_kernel(const float* __restrict__ A2, const uint4* __restrict__ wimg,
                     const float* __restrict__ bias, const float* __restrict__ wfc,
                     const float* __restrict__ bfc, float* __restrict__ out, int nn)
{
    extern __shared__ char smem[];
    uint32_t sb = smem_u32(smem);
    const int tid = threadIdx.x;
    const int lane = tid & 31, wid = tid >> 5;
    const int g = lane >> 2, t4 = lane & 3;
    const int wm = wid & 7, wn = wid >> 3;
    const int rowBase = blockIdx.x * 256;
    float* bias_s = (float*)(smem + OFF_BIAS);
    float* wfc_s  = (float*)(smem + OFF_WFC);
    float* fc_s   = (float*)(smem + OFF_FC);

    // stage W images (hi + lo contiguous: 8704 uint4)
    {
        uint4* dst = (uint4*)smem;
#pragma unroll
        for (int i = 0; i < 17; i++) {
            int idx = tid + 512 * i;
            dst[idx] = __ldg(wimg + idx);
        }
    }
    if (tid < 128) {
        bias_s[tid] = __ldg(bias + tid);
        wfc_s[tid] = EPI ? __ldg(wfc + tid) : 0.f;
    }
    if (EPI && tid < 256) fc_s[tid] = 0.f;
    __syncthreads();

    float acc[2][8][4];
#pragma unroll
    for (int mi = 0; mi < 2; mi++)
#pragma unroll
        for (int ni = 0; ni < 8; ni++)
#pragma unroll
            for (int q = 0; q < 4; q++) acc[mi][ni][q] = 0.f;

    const float4 fz4 = make_float4(0.f, 0.f, 0.f, 0.f);
    const int row0b = rowBase + wm * 32 + g;

    // one half of the reduction: 8 k-steps over one A source. kofs selects
    // the W-image k range (0 for agg half, 8 for A2 half).
    auto khalf = [&](const float* base, int kofs) {
#pragma unroll
        for (int kg = 0; kg < 8; kg++) {
            const int f4off = kg * 4 + t4;
            uint32_t ah[2][4], al[2][4];
#pragma unroll
            for (int mi = 0; mi < 2; mi++) {
                int row0 = row0b + mi * 16;
                int row1 = row0 + 8;
                float4 F0 = (row0 < nn)
                    ? __ldg((const float4*)(base + (size_t)row0 * 128) + f4off) : fz4;
                float4 F1 = (row1 < nn)
                    ? __ldg((const float4*)(base + (size_t)row1 * 128) + f4off) : fz4;
                cvt_hl(F0.x, F0.y, ah[mi][0], al[mi][0]);
                cvt_hl(F1.x, F1.y, ah[mi][1], al[mi][1]);
                cvt_hl(F0.z, F0.w, ah[mi][2], al[mi][2]);
                cvt_hl(F1.z, F1.w, ah[mi][3], al[mi][3]);
            }
#pragma unroll
            for (int ni = 0; ni < 8; ni++) {
                uint2 BH, BL;
                uint32_t bo = (uint32_t)(wn * 64 + ni * 8 + g) * 544
                            + (kg + kofs) * 32 + t4 * 8;
                lds64(BH.x, BH.y, sb + OFF_W_HI + bo);
                lds64(BL.x, BL.y, sb + OFF_W_LO + bo);
#pragma unroll
                for (int mi = 0; mi < 2; mi++) {
                    mma_bf16(acc[mi][ni], ah[mi][0], ah[mi][1], ah[mi][2], ah[mi][3],
                             BH.x, BH.y);
                    mma_bf16(acc[mi][ni], al[mi][0], al[mi][1], al[mi][2], al[mi][3],
                             BH.x, BH.y);
                    mma_bf16(acc[mi][ni], ah[mi][0], ah[mi][1], ah[mi][2], ah[mi][3],
                             BL.x, BL.y);
                }
            }
        }
    };
    khalf((const float*)g_agg4, 0);
    khalf(A2, 8);

    // ---- epilogue ----
    if (EPI == 0) {
#pragma unroll
        for (int mi = 0; mi < 2; mi++)
#pragma unroll
            for (int ni = 0; ni < 8; ni++) {
                int rowA = rowBase + wm * 32 + mi * 16 + g;
                int nf = wn * 64 + ni * 8 + 2 * t4;
                float b0 = bias_s[nf], b1 = bias_s[nf + 1];
                float v0 = fmaxf(acc[mi][ni][0] + b0, 0.f);
                float v1 = fmaxf(acc[mi][ni][1] + b1, 0.f);
                float v2 = fmaxf(acc[mi][ni][2] + b0, 0.f);
                float v3 = fmaxf(acc[mi][ni][3] + b1, 0.f);
                if (rowA < nn)
                    *(float2*)(out + (size_t)rowA * 128 + nf) = make_float2(v0, v1);
                if (rowA + 8 < nn)
                    *(float2*)(out + (size_t)(rowA + 8) * 128 + nf) = make_float2(v2, v3);
            }
    } else {
#pragma unroll
        for (int mi = 0; mi < 2; mi++) {
            float pA = 0.f, pB = 0.f;
#pragma unroll
            for (int ni = 0; ni < 8; ni++) {
                int nf = wn * 64 + ni * 8 + 2 * t4;
                float b0 = bias_s[nf], b1 = bias_s[nf + 1];
                float w0 = wfc_s[nf], w1 = wfc_s[nf + 1];
                pA += fmaxf(acc[mi][ni][0] + b0, 0.f) * w0
                    + fmaxf(acc[mi][ni][1] + b1, 0.f) * w1;
                pB += fmaxf(acc[mi][ni][2] + b0, 0.f) * w0
                    + fmaxf(acc[mi][ni][3] + b1, 0.f) * w1;
            }
            pA += __shfl_xor_sync(0xffffffffu, pA, 1);
            pA += __shfl_xor_sync(0xffffffffu, pA, 2);
            pB += __shfl_xor_sync(0xffffffffu, pB, 1);
            pB += __shfl_xor_sync(0xffffffffu, pB, 2);
            if (t4 == 0) {
                atomicAdd(&fc_s[wm * 32 + mi * 16 + g], pA);
                atomicAdd(&fc_s[wm * 32 + mi * 16 + g + 8], pB);
            }
        }
        __syncthreads();
        if (tid < 256) {
            int row = rowBase + tid;
            if (row < nn)
                out[row] = 1.0f / (1.0f + __expf(-(fc_s[tid] + __ldg(bfc))));
        }
    }
}

// ======================= launch sequence ===================================
extern "C" void kernel_launch(void* const* d_in, const int* in_sizes, int n_in,
                              void* d_out, int out_size)
{
    const float* x   = (const float*)d_in[0];
    const void*  ei  = d_in[1];
    const float* W1l = (const float*)d_in[2];
    const float* W1r = (const float*)d_in[3];
    const float* b1  = (const float*)d_in[4];
    const float* W2l = (const float*)d_in[5];
    const float* W2r = (const float*)d_in[6];
    const float* b2  = (const float*)d_in[7];
    const float* Wfc = (const float*)d_in[8];
    const float* bfc = (const float*)d_in[9];
    float*       out = (float*)d_out;

    int n = in_sizes[0] / 128;
    int E = in_sizes[1] / 2;

    float* h1_ptr = nullptr;
    cudaGetSymbolAddress((void**)&h1_ptr, g_h14);
    uint4* wimg_ptr = nullptr;
    cudaGetSymbolAddress((void**)&wimg_ptr, g_wimg);

    cudaFuncSetAttribute(mma_gemm_kernel<0>,
                         cudaFuncAttributeMaxDynamicSharedMemorySize, MMA_SMEM);
    cudaFuncSetAttribute(mma_gemm_kernel<1>,
                         cudaFuncAttributeMaxDynamicSharedMemorySize, MMA_SMEM);

    int gemmBlocks = (n + 255) / 256;
    int nb = (n + 255) / 256;
    int gatherBlocks = (n * 32 + 255) / 256;

    // setup (probe + zero fill + W prep), then slot-CSR fill
    setup_prep_kernel<<<nb, 256>>>(ei, n, W1l, W1r, W2l, W2r);   // 0
    fill_kernel<<<1024, 256>>>(ei, E);                            // 1

    // layer 1
    gather_kernel<<<gatherBlocks, 256>>>(x, n);                   // 2
    mma_gemm_kernel<0><<<gemmBlocks, 512, MMA_SMEM>>>(            // 3 <- ncu
        x, wimg_ptr, b1, nullptr, nullptr, h1_ptr, n);

    // layer 2 + FC head
    gather_kernel<<<gatherBlocks, 256>>>(h1_ptr, n);              // 4
    mma_gemm_kernel<1><<<gemmBlocks, 512, MMA_SMEM>>>(            // 5
        h1_ptr, wimg_ptr + 8704, b2, Wfc, bfc, out, n);
}

// round 14
// speedup vs baseline: 1.1436x; 1.0110x over previous
#include <cuda_runtime.h>
#include <cuda_bf16.h>
#include <math.h>
#include <stdint.h>

// ---------------------------------------------------------------------------
// FraudGraphSAGE: 2-layer GraphSAGE (mean agg) + FC sigmoid head.
// Aggregation: slot-CSR gather (fixed 64 slots/node, no f32 atomics).
// GEMMs: mma.sync m16n8k16 bf16-split (hi=truncate/lo=residual), fp32 accum.
//   M-tile 256/CTA, 512 threads. A via one LDG.128/row/kstep with hoisted
//   clamped row pointers (immediate-offset LDGs, no per-kstep address math);
//   B via conflict-free LDS.64 pairs at immediate offsets. No mainloop
//   barriers.
// ---------------------------------------------------------------------------

#define NMAX 100000
#define SLOTS 64

__device__ float4 g_agg4[(size_t)NMAX * 32];
__device__ float4 g_h14[(size_t)NMAX * 32];
__device__ int    g_fill[NMAX];
__device__ int    g_csr[(size_t)NMAX * SLOTS];
__device__ int    g_idx_is64;
// W images: [layer][hi=0/lo=1][69632B]: [n=128][544B]: per ksg (32B):
//   4x8B sub-blocks; sub-block t4 = bf16 phys k {4t4,4t4+1,4t4+2,4t4+3}.
__device__ uint4  g_wimg[2][2][4352];

// ======================= helpers ===========================================
__device__ __forceinline__ uint32_t smem_u32(const void* p) {
    uint32_t a;
    asm("{ .reg .u64 t; cvta.to.shared.u64 t, %1; cvt.u32.u64 %0, t; }"
        : "=r"(a) : "l"(p));
    return a;
}
__device__ __forceinline__ void lds64(uint32_t& x, uint32_t& y, uint32_t addr) {
    asm volatile("ld.shared.v2.b32 {%0,%1}, [%2];" : "=r"(x), "=r"(y) : "r"(addr));
}
__device__ __forceinline__ void mma_bf16(float* c, uint32_t a0, uint32_t a1,
                                         uint32_t a2, uint32_t a3,
                                         uint32_t b0, uint32_t b1) {
    asm volatile(
        "mma.sync.aligned.m16n8k16.row.col.f32.bf16.bf16.f32 "
        "{%0,%1,%2,%3}, {%4,%5,%6,%7}, {%8,%9}, {%0,%1,%2,%3};"
        : "+f"(c[0]), "+f"(c[1]), "+f"(c[2]), "+f"(c[3])
        : "r"(a0), "r"(a1), "r"(a2), "r"(a3), "r"(b0), "r"(b1));
}
// (x,y) -> (bf16x2 hi, bf16x2 lo).  hi = truncated top-16-bits (one PRMT for
// the pair); lo = rn(residual) via packed cvt. Residual is exact, so total
// split error ~2^-17 per value.
__device__ __forceinline__ void cvt_hl(float x, float y, uint32_t& hi, uint32_t& lo) {
    uint32_t xu = __float_as_uint(x), yu = __float_as_uint(y);
    asm("prmt.b32 %0, %1, %2, 0x7632;" : "=r"(hi) : "r"(xu), "r"(yu));
    float lx = x - __uint_as_float(xu & 0xFFFF0000u);
    float ly = y - __uint_as_float(yu & 0xFFFF0000u);
    asm("cvt.rn.bf16x2.f32 %0, %1, %2;" : "=r"(lo) : "f"(ly), "f"(lx));
}

__device__ __forceinline__ int edge_dst(const void* ei, int E, int e, int is64)
{
    if (is64) return (int)__ldg(((const long long*)ei) + E + e);
    return __ldg(((const int*)ei) + E + e);
}
__device__ __forceinline__ int edge_src(const void* ei, int E, int e, int is64)
{
    if (is64) return (int)__ldg(((const long long*)ei) + e);
    return __ldg(((const int*)ei) + e);
}

// ======================= setup: probe + zero fill + W prep =================
__global__ void setup_prep_kernel(const void* ei, int n,
                                  const float* __restrict__ W1l, const float* __restrict__ W1r,
                                  const float* __restrict__ W2l, const float* __restrict__ W2r)
{
    int t = blockIdx.x * blockDim.x + threadIdx.x;
    if (t < n) g_fill[t] = 0;
    if (t == 0) {
        const unsigned long long* p = (const unsigned long long*)ei;
        int is64 = 1;
        for (int k = 0; k < 8; k++)
            if (p[k] >> 32) { is64 = 0; break; }
        g_idx_is64 = is64;
    }
    if (t < 2 * 128 * 256) {
        int layer = t >> 15;
        int rem = t & 32767;
        int nrow = rem >> 8;
        int k = rem & 255;          // physical reduction index
        const float* Wl = layer ? W2l : W1l;
        const float* Wr = layer ? W2r : W1r;
        float v = (k < 128) ? __ldg(Wl + k * 128 + nrow)
                            : __ldg(Wr + (k - 128) * 128 + nrow);
        __nv_bfloat16 hh = __float2bfloat16(v);
        __nv_bfloat16 ll = __float2bfloat16(v - __bfloat162float(hh));
        int ksg = k >> 4, j = k & 15;
        // sub-block (j>>2)=t4 gets phys k 4*t4 + (j&3)
        uint32_t off = (uint32_t)nrow * 544 + ksg * 32 + (j >> 2) * 8 + (j & 3) * 2;
        *(__nv_bfloat16*)((char*)&g_wimg[layer][0][0] + off) = hh;
        *(__nv_bfloat16*)((char*)&g_wimg[layer][1][0] + off) = ll;
    }
}

// fill slot-CSR; g_fill ends up holding the degree
__global__ void fill_kernel(const void* __restrict__ ei, int E)
{
    int is64 = g_idx_is64;
    int tid = blockIdx.x * blockDim.x + threadIdx.x;
    int stride = gridDim.x * blockDim.x;
    for (int e = tid; e < E; e += stride) {
        int d = edge_dst(ei, E, e, is64);
        int s = edge_src(ei, E, e, is64);
        int slot = atomicAdd(&g_fill[d], 1);
        if (slot < SLOTS) g_csr[(size_t)d * SLOTS + slot] = s;
    }
}

// ======================= Gather (mean aggregate) ===========================
__global__ void gather_kernel(const float* __restrict__ feat, int n)
{
    int lane = threadIdx.x & 31;
    int w = (blockIdx.x * blockDim.x + threadIdx.x) >> 5;
    if (w >= n) return;
    const int* lst = g_csr + (size_t)w * SLOTS;
    int cnt = min(g_fill[w], SLOTS);
    const float4* f4 = (const float4*)feat;
    float4 a0 = make_float4(0.f, 0.f, 0.f, 0.f), a1 = a0, a2 = a0, a3 = a0;
    int j = 0;
    for (; j + 4 <= cnt; j += 4) {
        int s0 = __ldg(lst + j);
        int s1 = __ldg(lst + j + 1);
        int s2 = __ldg(lst + j + 2);
        int s3 = __ldg(lst + j + 3);
        float4 v0 = __ldg(f4 + (size_t)s0 * 32 + lane);
        float4 v1 = __ldg(f4 + (size_t)s1 * 32 + lane);
        float4 v2 = __ldg(f4 + (size_t)s2 * 32 + lane);
        float4 v3 = __ldg(f4 + (size_t)s3 * 32 + lane);
        a0.x += v0.x; a0.y += v0.y; a0.z += v0.z; a0.w += v0.w;
        a1.x += v1.x; a1.y += v1.y; a1.z += v1.z; a1.w += v1.w;
        a2.x += v2.x; a2.y += v2.y; a2.z += v2.z; a2.w += v2.w;
        a3.x += v3.x; a3.y += v3.y; a3.z += v3.z; a3.w += v3.w;
    }
    for (; j < cnt; j++) {
        int s = __ldg(lst + j);
        float4 v = __ldg(f4 + (size_t)s * 32 + lane);
        a0.x += v.x; a0.y += v.y; a0.z += v.z; a0.w += v.w;
    }
    float inv = 1.0f / fmaxf((float)cnt, 1.0f);
    float4 rr;
    rr.x = (a0.x + a1.x + a2.x + a3.x) * inv;
    rr.y = (a0.y + a1.y + a2.y + a3.y) * inv;
    rr.z = (a0.z + a1.z + a2.z + a3.z) * inv;
    rr.w = (a0.w + a1.w + a2.w + a3.w) * inv;
    g_agg4[(size_t)w * 32 + lane] = rr;
}

// ======================= mma.sync GEMM =====================================
// C[i][0:128] = relu([agg_i | A2_i](256) @ W(256x128) + bias), bf16 split:
// A_hi*W_hi + A_lo*W_hi + A_hi*W_lo, fp32 accum.
// 512 thr, 16 warps: wm=wid&7 -> m32 (mi=2), wn=wid>>3 -> n64 (ni=8).
// Row pointers hoisted + clamped (OOB rows read row nn-1; their accs are
// never stored), so the k-loop is immediate-offset LDG/LDS only.
#define OFF_W_HI 0
#define OFF_W_LO 69632
#define OFF_BIAS 139264
#define OFF_WFC  139776
#define OFF_FC   140288
#define MMA_SMEM 141312

template <int EPI>
__global__ __launch_bounds__(512, 1)
void mma_gemm_kernel(const float* __restrict__ A2, const uint4* __restrict__ wimg,
                     const float* __restrict__ bias, const float* __restrict__ wfc,
                     const float* __restrict__ bfc, float* __restrict__ out, int nn)
{
    extern __shared__ char smem[];
    uint32_t sb = smem_u32(smem);
    const int tid = threadIdx.x;
    const int lane = tid & 31, wid = tid >> 5;
    const int g = lane >> 2, t4 = lane & 3;
    const int wm = wid & 7, wn = wid >> 3;
    const int rowBase = blockIdx.x * 256;
    float* bias_s = (float*)(smem + OFF_BIAS);
    float* wfc_s  = (float*)(smem + OFF_WFC);
    float* fc_s   = (float*)(smem + OFF_FC);

    // stage W images (hi + lo contiguous: 8704 uint4)
    {
        uint4* dst = (uint4*)smem;
#pragma unroll
        for (int i = 0; i < 17; i++) {
            int idx = tid + 512 * i;
            dst[idx] = __ldg(wimg + idx);
        }
    }
    if (tid < 128) {
        bias_s[tid] = __ldg(bias + tid);
        wfc_s[tid] = EPI ? __ldg(wfc + tid) : 0.f;
    }
    if (EPI && tid < 256) fc_s[tid] = 0.f;
    __syncthreads();

    float acc[2][8][4];
#pragma unroll
    for (int mi = 0; mi < 2; mi++)
#pragma unroll
        for (int ni = 0; ni < 8; ni++)
#pragma unroll
            for (int q = 0; q < 4; q++) acc[mi][ni][q] = 0.f;

    const int row0b = rowBase + wm * 32 + g;
    // B smem base: per-ni offset ni*4352 and per-k offset k*32 are immediates.
    const uint32_t bBase = sb + (uint32_t)(wn * 64 + g) * 544 + t4 * 8;

    // one half of the reduction: 8 k-steps over one A source. kofs selects
    // the W-image k range (0 for agg half, 8 for A2 half).
    auto khalf = [&](const float* base, int kofs) {
        // hoisted clamped row pointers (float4 units, + t4 lane offset)
        const float4* pr[2][2];
#pragma unroll
        for (int mi = 0; mi < 2; mi++) {
            int r0 = min(row0b + mi * 16, nn - 1);
            int r1 = min(row0b + mi * 16 + 8, nn - 1);
            pr[mi][0] = (const float4*)(base + (size_t)r0 * 128) + t4;
            pr[mi][1] = (const float4*)(base + (size_t)r1 * 128) + t4;
        }
#pragma unroll
        for (int kg = 0; kg < 8; kg++) {
            uint32_t ah[2][4], al[2][4];
#pragma unroll
            for (int mi = 0; mi < 2; mi++) {
                float4 F0 = __ldg(pr[mi][0] + kg * 4);
                float4 F1 = __ldg(pr[mi][1] + kg * 4);
                cvt_hl(F0.x, F0.y, ah[mi][0], al[mi][0]);
                cvt_hl(F1.x, F1.y, ah[mi][1], al[mi][1]);
                cvt_hl(F0.z, F0.w, ah[mi][2], al[mi][2]);
                cvt_hl(F1.z, F1.w, ah[mi][3], al[mi][3]);
            }
            const uint32_t kO = (uint32_t)(kg + kofs) * 32;
#pragma unroll
            for (int ni = 0; ni < 8; ni++) {
                uint2 BH, BL;
                lds64(BH.x, BH.y, bBase + OFF_W_HI + ni * 4352 + kO);
                lds64(BL.x, BL.y, bBase + OFF_W_LO + ni * 4352 + kO);
#pragma unroll
                for (int mi = 0; mi < 2; mi++) {
                    mma_bf16(acc[mi][ni], ah[mi][0], ah[mi][1], ah[mi][2], ah[mi][3],
                             BH.x, BH.y);
                    mma_bf16(acc[mi][ni], al[mi][0], al[mi][1], al[mi][2], al[mi][3],
                             BH.x, BH.y);
                    mma_bf16(acc[mi][ni], ah[mi][0], ah[mi][1], ah[mi][2], ah[mi][3],
                             BL.x, BL.y);
                }
            }
        }
    };
    khalf((const float*)g_agg4, 0);
    khalf(A2, 8);

    // ---- epilogue ----
    if (EPI == 0) {
#pragma unroll
        for (int mi = 0; mi < 2; mi++)
#pragma unroll
            for (int ni = 0; ni < 8; ni++) {
                int rowA = rowBase + wm * 32 + mi * 16 + g;
                int nf = wn * 64 + ni * 8 + 2 * t4;
                float b0 = bias_s[nf], b1 = bias_s[nf + 1];
                float v0 = fmaxf(acc[mi][ni][0] + b0, 0.f);
                float v1 = fmaxf(acc[mi][ni][1] + b1, 0.f);
                float v2 = fmaxf(acc[mi][ni][2] + b0, 0.f);
                float v3 = fmaxf(acc[mi][ni][3] + b1, 0.f);
                if (rowA < nn)
                    *(float2*)(out + (size_t)rowA * 128 + nf) = make_float2(v0, v1);
                if (rowA + 8 < nn)
                    *(float2*)(out + (size_t)(rowA + 8) * 128 + nf) = make_float2(v2, v3);
            }
    } else {
#pragma unroll
        for (int mi = 0; mi < 2; mi++) {
            float pA = 0.f, pB = 0.f;
#pragma unroll
            for (int ni = 0; ni < 8; ni++) {
                int nf = wn * 64 + ni * 8 + 2 * t4;
                float b0 = bias_s[nf], b1 = bias_s[nf + 1];
                float w0 = wfc_s[nf], w1 = wfc_s[nf + 1];
                pA += fmaxf(acc[mi][ni][0] + b0, 0.f) * w0
                    + fmaxf(acc[mi][ni][1] + b1, 0.f) * w1;
                pB += fmaxf(acc[mi][ni][2] + b0, 0.f) * w0
                    + fmaxf(acc[mi][ni][3] + b1, 0.f) * w1;
            }
            pA += __shfl_xor_sync(0xffffffffu, pA, 1);
            pA += __shfl_xor_sync(0xffffffffu, pA, 2);
            pB += __shfl_xor_sync(0xffffffffu, pB, 1);
            pB += __shfl_xor_sync(0xffffffffu, pB, 2);
            if (t4 == 0) {
                atomicAdd(&fc_s[wm * 32 + mi * 16 + g], pA);
                atomicAdd(&fc_s[wm * 32 + mi * 16 + g + 8], pB);
            }
        }
        __syncthreads();
        if (tid < 256) {
            int row = rowBase + tid;
            if (row < nn)
                out[row] = 1.0f / (1.0f + __expf(-(fc_s[tid] + __ldg(bfc))));
        }
    }
}

// ======================= launch sequence ===================================
extern "C" void kernel_launch(void* const* d_in, const int* in_sizes, int n_in,
                              void* d_out, int out_size)
{
    const float* x   = (const float*)d_in[0];
    const void*  ei  = d_in[1];
    const float* W1l = (const float*)d_in[2];
    const float* W1r = (const float*)d_in[3];
    const float* b1  = (const float*)d_in[4];
    const float* W2l = (const float*)d_in[5];
    const float* W2r = (const float*)d_in[6];
    const float* b2  = (const float*)d_in[7];
    const float* Wfc = (const float*)d_in[8];
    const float* bfc = (const float*)d_in[9];
    float*       out = (float*)d_out;

    int n = in_sizes[0] / 128;
    int E = in_sizes[1] / 2;

    float* h1_ptr = nullptr;
    cudaGetSymbolAddress((void**)&h1_ptr, g_h14);
    uint4* wimg_ptr = nullptr;
    cudaGetSymbolAddress((void**)&wimg_ptr, g_wimg);

    cudaFuncSetAttribute(mma_gemm_kernel<0>,
                         cudaFuncAttributeMaxDynamicSharedMemorySize, MMA_SMEM);
    cudaFuncSetAttribute(mma_gemm_kernel<1>,
                         cudaFuncAttributeMaxDynamicSharedMemorySize, MMA_SMEM);

    int gemmBlocks = (n + 255) / 256;
    int nb = (n + 255) / 256;
    int gatherBlocks = (n * 32 + 255) / 256;

    // setup (probe + zero fill + W prep), then slot-CSR fill
    setup_prep_kernel<<<nb, 256>>>(ei, n, W1l, W1r, W2l, W2r);   // 0
    fill_kernel<<<1024, 256>>>(ei, E);                            // 1

    // layer 1
    gather_kernel<<<gatherBlocks, 256>>>(x, n);                   // 2
    mma_gemm_kernel<0><<<gemmBlocks, 512, MMA_SMEM>>>(            // 3 <- ncu
        x, wimg_ptr, b1, nullptr, nullptr, h1_ptr, n);

    // layer 2 + FC head
    gather_kernel<<<gatherBlocks, 256>>>(h1_ptr, n);              // 4
    mma_gemm_kernel<1><<<gemmBlocks, 512, MMA_SMEM>>>(            // 5
        h1_ptr, wimg_ptr + 8704, b2, Wfc, bfc, out, n);
}